// round 16
// baseline (speedup 1.0000x reference)
#include <cuda_runtime.h>
#include <cstdint>

#define DIM 85
#define B_ROWS 262144
#define TROWS 32
#define THREADS 128
#define NT (B_ROWS / TROWS)        // 8192 tiles
#define GRID 592                   // 4 persistent CTAs per SM
#define TILE_F (TROWS * DIM)       // 2720 floats per array per tile
#define TILE_B (TILE_F * 4)        // 10880 bytes
#define STAGE_B (2 * TILE_B)       // 21760 bytes (in + tg)
#define PF_AHEAD 4                 // prefetch distance (tiles, > pipeline depth 2)

#define OFF_MBAR 0                 // 2 mbarriers, 8 B each
#define OFF_SP   16                                  // [2][128] floats
#define OFF_ST   (OFF_SP + 2 * THREADS * 4)
#define OFF_SU   (OFF_ST + 2 * THREADS * 4)
#define OFF_DATA (OFF_SU + 2 * THREADS * 4)          // 3088 (16B aligned)
#define SMEM_TOTAL (OFF_DATA + 2 * STAGE_B)          // 46608 B -> 4 CTAs/SM

__device__ float g_partials[GRID];
__device__ int   g_count = 0;

__device__ __forceinline__ void mbar_init(uint32_t mbar, uint32_t cnt) {
    asm volatile("mbarrier.init.shared.b64 [%0], %1;" :: "r"(mbar), "r"(cnt) : "memory");
}
__device__ __forceinline__ void mbar_expect_tx(uint32_t mbar, uint32_t bytes) {
    asm volatile("mbarrier.arrive.expect_tx.shared.b64 _, [%0], %1;"
                 :: "r"(mbar), "r"(bytes) : "memory");
}
__device__ __forceinline__ void mbar_wait(uint32_t mbar, uint32_t parity) {
    asm volatile(
        "{\n\t"
        ".reg .pred P;\n\t"
        "W_%=:\n\t"
        "mbarrier.try_wait.parity.acquire.cta.shared::cta.b64 P, [%0], %1, 0x989680;\n\t"
        "@P bra D_%=;\n\t"
        "bra W_%=;\n\t"
        "D_%=:\n\t"
        "}" :: "r"(mbar), "r"(parity) : "memory");
}
__device__ __forceinline__ void bulk_g2s(uint32_t dst, const void* src,
                                         uint32_t bytes, uint32_t mbar) {
    asm volatile(
        "cp.async.bulk.shared::cta.global.mbarrier::complete_tx::bytes [%0], [%1], %2, [%3];"
        :: "r"(dst), "l"(src), "r"(bytes), "r"(mbar) : "memory");
}
__device__ __forceinline__ void l2_prefetch(const void* g) {
    asm volatile("prefetch.global.L2 [%0];" :: "l"(g));
}

__global__ __launch_bounds__(THREADS)
void qfd_pf(const float* __restrict__ in, const float* __restrict__ tg,
            float* __restrict__ out)
{
    extern __shared__ __align__(16) unsigned char smraw[];
    float* sP = (float*)(smraw + OFF_SP);        // [2][128]
    float* sT = (float*)(smraw + OFF_ST);
    float* sU = (float*)(smraw + OFF_SU);
    __shared__ float warp_part[THREADS / 32];
    __shared__ bool  s_is_last;

    const int tid  = threadIdx.x;
    const int lane = tid & 31;
    const int wg   = tid >> 5;                             // warp 0..3
    const int row  = tid & (TROWS - 1);                    // scan row 0..31
    const int kbeg = (wg == 0) ? 0 : (1 + 21 * wg);        // 0,22,43,64
    const int kcnt = (wg == 0) ? 22 : 21;
    const float fkbeg = (float)kbeg;
    const int roff = row * DIM + kbeg;

    const uint32_t mb0 = (uint32_t)__cvta_generic_to_shared(smraw + OFF_MBAR);
    const uint32_t data_s = (uint32_t)__cvta_generic_to_shared(smraw + OFF_DATA);

    if (tid == 0) {
        mbar_init(mb0, 1);
        mbar_init(mb0 + 8, 1);
        asm volatile("fence.proxy.async.shared::cta;" ::: "memory");
    }
    __syncthreads();

    // ---- prologue: prefetch tiles t0 (stage0) and t0+GRID (stage1) ----
    const int t0 = blockIdx.x;
    if (tid == 0) {
        mbar_expect_tx(mb0, STAGE_B);
        bulk_g2s(data_s,          in + (size_t)t0 * TILE_F, TILE_B, mb0);
        bulk_g2s(data_s + TILE_B, tg + (size_t)t0 * TILE_F, TILE_B, mb0);
        int t1 = t0 + GRID;
        if (t1 < NT) {
            mbar_expect_tx(mb0 + 8, STAGE_B);
            bulk_g2s(data_s + STAGE_B,          in + (size_t)t1 * TILE_F, TILE_B, mb0 + 8);
            bulk_g2s(data_s + STAGE_B + TILE_B, tg + (size_t)t1 * TILE_F, TILE_B, mb0 + 8);
        }
    }
    // L2-prefetch tiles t0+2G, t0+3G so the first in-loop TMA refills hit L2 too
    {
#pragma unroll
        for (int d = 2; d < PF_AHEAD; d++) {
            int tp = t0 + d * GRID;
            if (tp < NT) {
                const char* pin = (const char*)(in + (size_t)tp * TILE_F);
                const char* ptg = (const char*)(tg + (size_t)tp * TILE_F);
                if (tid < 85)                l2_prefetch(pin + (size_t)tid * 128);
                if (tid >= 43)               l2_prefetch(ptg + (size_t)(tid - 43) * 128);
            }
        }
    }

    float acc = 0.0f;

    int k = 0;
    for (int t = t0; t < NT; t += GRID, k++) {
        const int s  = k & 1;
        const int ph = (k >> 1) & 1;
        const int pp = (k & 1) * THREADS;                  // partials ping-pong

        // ---- L2 prefetch stream: tile t + PF_AHEAD*GRID (2 beyond TMA window) ----
        {
            int tp = t + PF_AHEAD * GRID;
            if (tp < NT) {
                const char* pin = (const char*)(in + (size_t)tp * TILE_F);
                const char* ptg = (const char*)(tg + (size_t)tp * TILE_F);
                if (tid < 85)                l2_prefetch(pin + (size_t)tid * 128);
                if (tid >= 43)               l2_prefetch(ptg + (size_t)(tid - 43) * 128);
            }
        }

        mbar_wait(mb0 + 8u * s, (uint32_t)ph);

        const float* in_sm = (const float*)(smraw + OFF_DATA + s * STAGE_B);
        const float* tg_sm = (const float*)(smraw + OFF_DATA + s * STAGE_B + TILE_B);
        const float* ri = in_sm + roff;
        const float* rt = tg_sm + roff;

        float P = 0.0f, Tn = 0.0f, U = 0.0f;               // Tn = -T
#pragma unroll
        for (int kk = 0; kk < 22; kk++) {
            if (kk < kcnt) {
                float d  = fabsf(ri[kk] - rt[kk]);
                float fk = fkbeg + (float)kk;
                U  = fmaf(d, fmaf(fk, P, Tn), U);
                P += d;
                Tn = fmaf(-fk, d, Tn);
            }
        }
        sP[pp + tid] = P;
        sT[pp + tid] = -Tn;
        sU[pp + tid] = U;

        __syncthreads();                // single barrier per tile

        // refill stage s with tile t + 2*GRID (lane 8 — no combine duty)
        if (tid == 8) {
            int tn = t + 2 * GRID;
            if (tn < NT) {
                uint32_t mb = mb0 + 8u * s;
                uint32_t ds = data_s + (uint32_t)(s * STAGE_B);
                mbar_expect_tx(mb, STAGE_B);
                bulk_g2s(ds,          in + (size_t)tn * TILE_F, TILE_B, mb);
                bulk_g2s(ds + TILE_B, tg + (size_t)tn * TILE_F, TILE_B, mb);
            }
        }

        // per-row combine spread over 4 warps (lanes 0..7; warp wg: rows 8wg..8wg+7)
        if (lane < 8) {
            const int crow = wg * 8 + lane;
            float P0 = sP[pp + crow],      P1 = sP[pp + 32 + crow];
            float P2 = sP[pp + 64 + crow], P3 = sP[pp + 96 + crow];
            float T0 = sT[pp + crow],      T1 = sT[pp + 32 + crow];
            float T2 = sT[pp + 64 + crow], T3 = sT[pp + 96 + crow];
            float Ut = (sU[pp + crow] + sU[pp + 32 + crow])
                     + (sU[pp + 64 + crow] + sU[pp + 96 + crow]);
            Ut = fmaf(P0, T1, fmaf(-T0, P1, Ut));
            Ut = fmaf(P0, T2, fmaf(-T0, P2, Ut));
            Ut = fmaf(P0, T3, fmaf(-T0, P3, Ut));
            Ut = fmaf(P1, T2, fmaf(-T1, P2, Ut));
            Ut = fmaf(P1, T3, fmaf(-T1, P3, Ut));
            Ut = fmaf(P2, T3, fmaf(-T2, P3, Ut));
            float S = (P0 + P1) + (P2 + P3);
            acc += fmaf(S, S, -(2.0f / (float)DIM) * Ut);
        }
    }

    // ---- deterministic block reduce ----
    __syncthreads();
    for (int o = 16; o; o >>= 1)
        acc += __shfl_down_sync(0xffffffffu, acc, o);
    if (lane == 0)
        warp_part[wg] = acc;
    __syncthreads();

    if (tid == 0) {
        float sum = (warp_part[0] + warp_part[1]) + (warp_part[2] + warp_part[3]);
        g_partials[blockIdx.x] = sum;
        __threadfence();
        int old = atomicAdd(&g_count, 1);
        s_is_last = (old == GRID - 1);
    }
    __syncthreads();

    // ---- last-arriving block: final deterministic reduce in double ----
    if (s_is_last) {
        __shared__ double sd[THREADS];
        double a = 0.0;
#pragma unroll
        for (int j = 0; j < (GRID + THREADS - 1) / THREADS; j++) {
            int i = tid + j * THREADS;
            if (i < GRID) a += (double)g_partials[i];
        }
        sd[tid] = a;
        __syncthreads();
        for (int o = THREADS / 2; o; o >>= 1) {
            if (tid < o) sd[tid] += sd[tid + o];
            __syncthreads();
        }
        if (tid == 0) {
            out[0] = (float)(0.1 * sd[0]);
            g_count = 0;                          // self-reset for next replay
        }
    }
}

extern "C" void kernel_launch(void* const* d_in, const int* in_sizes, int n_in,
                              void* d_out, int out_size)
{
    const float* in = (const float*)d_in[0];
    const float* tg = (const float*)d_in[1];
    float* out = (float*)d_out;

    cudaFuncSetAttribute(qfd_pf,
                         cudaFuncAttributeMaxDynamicSharedMemorySize, SMEM_TOTAL);
    qfd_pf<<<GRID, THREADS, SMEM_TOTAL>>>(in, tg, out);
}

// round 17
// speedup vs baseline: 1.0838x; 1.0838x over previous
#include <cuda_runtime.h>
#include <cstdint>

#define DIM 85
#define B_ROWS 262144
#define TROWS 64
#define THREADS 256
#define NT (B_ROWS / TROWS)        // 4096 tiles
#define GRID 296                   // 2 persistent CTAs per SM
#define TILE_F (TROWS * DIM)       // 5440 floats per array per tile
#define TILE_B (TILE_F * 4)        // 21760 bytes
#define STAGE_B (2 * TILE_B)       // 43520 bytes (in + tg)

#define OFF_MBAR 0                 // 2 mbarriers, 8 B each
#define OFF_SP   16                                  // [2][256] floats
#define OFF_ST   (OFF_SP + 2 * THREADS * 4)
#define OFF_SU   (OFF_ST + 2 * THREADS * 4)
#define OFF_DATA (OFF_SU + 2 * THREADS * 4)          // 6160 (16B aligned)
#define SMEM_TOTAL (OFF_DATA + 2 * STAGE_B)          // 93200 B -> 2 CTAs/SM

__device__ float g_partials[GRID];
__device__ int   g_count = 0;

__device__ __forceinline__ void mbar_init(uint32_t mbar, uint32_t cnt) {
    asm volatile("mbarrier.init.shared.b64 [%0], %1;" :: "r"(mbar), "r"(cnt) : "memory");
}
__device__ __forceinline__ void mbar_expect_tx(uint32_t mbar, uint32_t bytes) {
    asm volatile("mbarrier.arrive.expect_tx.shared.b64 _, [%0], %1;"
                 :: "r"(mbar), "r"(bytes) : "memory");
}
__device__ __forceinline__ void mbar_wait(uint32_t mbar, uint32_t parity) {
    asm volatile(
        "{\n\t"
        ".reg .pred P;\n\t"
        "W_%=:\n\t"
        "mbarrier.try_wait.parity.acquire.cta.shared::cta.b64 P, [%0], %1, 0x989680;\n\t"
        "@P bra D_%=;\n\t"
        "bra W_%=;\n\t"
        "D_%=:\n\t"
        "}" :: "r"(mbar), "r"(parity) : "memory");
}
__device__ __forceinline__ void bulk_g2s(uint32_t dst, const void* src,
                                         uint32_t bytes, uint32_t mbar) {
    asm volatile(
        "cp.async.bulk.shared::cta.global.mbarrier::complete_tx::bytes [%0], [%1], %2, [%3];"
        :: "r"(dst), "l"(src), "r"(bytes), "r"(mbar) : "memory");
}

__global__ __launch_bounds__(THREADS)
void qfd_final(const float* __restrict__ in, const float* __restrict__ tg,
               float* __restrict__ out)
{
    extern __shared__ __align__(16) unsigned char smraw[];
    float* sP = (float*)(smraw + OFF_SP);        // [2][256]
    float* sT = (float*)(smraw + OFF_ST);
    float* sU = (float*)(smraw + OFF_SU);
    __shared__ float warp_part[THREADS / 32];
    __shared__ bool  s_is_last;

    const int tid  = threadIdx.x;
    const int lane = tid & 31;
    const int wg   = tid >> 5;                             // warp 0..7
    // scan mapping (R9-validated, conflict-free): warp = 32 rows, same segment
    const int row  = tid & (TROWS - 1);                    // 0..63
    const int seg  = tid >> 6;                             // 0..3
    const int kbeg = (seg == 0) ? 0 : (1 + 21 * seg);      // 0,22,43,64
    const int kcnt = (seg == 0) ? 22 : 21;
    const float fkbeg = (float)kbeg;
    const int roff = row * DIM + kbeg;

    const uint32_t mb0 = (uint32_t)__cvta_generic_to_shared(smraw + OFF_MBAR);
    const uint32_t data_s = (uint32_t)__cvta_generic_to_shared(smraw + OFF_DATA);

    if (tid == 0) {
        mbar_init(mb0, 1);
        mbar_init(mb0 + 8, 1);
        asm volatile("fence.proxy.async.shared::cta;" ::: "memory");
    }
    __syncthreads();

    // ---- prologue: prefetch tiles t0 (stage0) and t0+GRID (stage1) ----
    const int t0 = blockIdx.x;
    if (tid == 0) {
        mbar_expect_tx(mb0, STAGE_B);
        bulk_g2s(data_s,          in + (size_t)t0 * TILE_F, TILE_B, mb0);
        bulk_g2s(data_s + TILE_B, tg + (size_t)t0 * TILE_F, TILE_B, mb0);
        int t1 = t0 + GRID;
        if (t1 < NT) {
            mbar_expect_tx(mb0 + 8, STAGE_B);
            bulk_g2s(data_s + STAGE_B,          in + (size_t)t1 * TILE_F, TILE_B, mb0 + 8);
            bulk_g2s(data_s + STAGE_B + TILE_B, tg + (size_t)t1 * TILE_F, TILE_B, mb0 + 8);
        }
    }

    float acc = 0.0f;

    int k = 0;
    for (int t = t0; t < NT; t += GRID, k++) {
        const int s  = k & 1;
        const int ph = (k >> 1) & 1;
        const int pp = (k & 1) * THREADS;                  // partials ping-pong
        mbar_wait(mb0 + 8u * s, (uint32_t)ph);

        const float* in_sm = (const float*)(smraw + OFF_DATA + s * STAGE_B);
        const float* tg_sm = (const float*)(smraw + OFF_DATA + s * STAGE_B + TILE_B);
        const float* ri = in_sm + roff;
        const float* rt = tg_sm + roff;

        float P = 0.0f, Tn = 0.0f, U = 0.0f;               // Tn = -T
#pragma unroll
        for (int kk = 0; kk < 22; kk++) {
            if (kk < kcnt) {
                float d  = fabsf(ri[kk] - rt[kk]);
                float fk = fkbeg + (float)kk;
                U  = fmaf(d, fmaf(fk, P, Tn), U);
                P += d;
                Tn = fmaf(-fk, d, Tn);
            }
        }
        sP[pp + tid] = P;
        sT[pp + tid] = -Tn;
        sU[pp + tid] = U;

        __syncthreads();                // the ONLY barrier per tile:
                                        // stage s consumed; partials(pp) published

        // refill stage s with tile t + 2*GRID (lane 8 of warp 0 — no combine duty)
        if (tid == 8) {
            int tn = t + 2 * GRID;
            if (tn < NT) {
                uint32_t mb = mb0 + 8u * s;
                uint32_t ds = data_s + (uint32_t)(s * STAGE_B);
                mbar_expect_tx(mb, STAGE_B);
                bulk_g2s(ds,          in + (size_t)tn * TILE_F, TILE_B, mb);
                bulk_g2s(ds + TILE_B, tg + (size_t)tn * TILE_F, TILE_B, mb);
            }
        }

        // per-row combine spread over 8 warps (lanes 0..7; warp wg: rows 8wg..8wg+7).
        // Overlaps next tile's wait/scan; pp protected by the k+1 barrier.
        if (lane < 8) {
            const int crow = wg * 8 + lane;                // 0..63
            float P0 = sP[pp + crow],       P1 = sP[pp + 64 + crow];
            float P2 = sP[pp + 128 + crow], P3 = sP[pp + 192 + crow];
            float T0 = sT[pp + crow],       T1 = sT[pp + 64 + crow];
            float T2 = sT[pp + 128 + crow], T3 = sT[pp + 192 + crow];
            float Ut = (sU[pp + crow] + sU[pp + 64 + crow])
                     + (sU[pp + 128 + crow] + sU[pp + 192 + crow]);
            Ut = fmaf(P0, T1, fmaf(-T0, P1, Ut));
            Ut = fmaf(P0, T2, fmaf(-T0, P2, Ut));
            Ut = fmaf(P0, T3, fmaf(-T0, P3, Ut));
            Ut = fmaf(P1, T2, fmaf(-T1, P2, Ut));
            Ut = fmaf(P1, T3, fmaf(-T1, P3, Ut));
            Ut = fmaf(P2, T3, fmaf(-T2, P3, Ut));
            float S = (P0 + P1) + (P2 + P3);
            acc += fmaf(S, S, -(2.0f / (float)DIM) * Ut);
        }
    }

    // ---- deterministic block reduce ----
    __syncthreads();
    for (int o = 16; o; o >>= 1)
        acc += __shfl_down_sync(0xffffffffu, acc, o);
    if (lane == 0)
        warp_part[wg] = acc;
    __syncthreads();

    if (tid == 0) {
        float sum = 0.0f;
#pragma unroll
        for (int i = 0; i < THREADS / 32; i++)
            sum += warp_part[i];
        g_partials[blockIdx.x] = sum;
        __threadfence();
        int old = atomicAdd(&g_count, 1);
        s_is_last = (old == GRID - 1);
    }
    __syncthreads();

    // ---- last-arriving block: final deterministic reduce in double ----
    if (s_is_last) {
        __shared__ double sd[THREADS];
        double a = 0.0;
#pragma unroll
        for (int j = 0; j < (GRID + THREADS - 1) / THREADS; j++) {
            int i = tid + j * THREADS;
            if (i < GRID) a += (double)g_partials[i];
        }
        sd[tid] = a;
        __syncthreads();
        for (int o = THREADS / 2; o; o >>= 1) {
            if (tid < o) sd[tid] += sd[tid + o];
            __syncthreads();
        }
        if (tid == 0) {
            out[0] = (float)(0.1 * sd[0]);
            g_count = 0;                          // self-reset for next replay
        }
    }
}

extern "C" void kernel_launch(void* const* d_in, const int* in_sizes, int n_in,
                              void* d_out, int out_size)
{
    const float* in = (const float*)d_in[0];
    const float* tg = (const float*)d_in[1];
    float* out = (float*)d_out;

    cudaFuncSetAttribute(qfd_final,
                         cudaFuncAttributeMaxDynamicSharedMemorySize, SMEM_TOTAL);
    qfd_final<<<GRID, THREADS, SMEM_TOTAL>>>(in, tg, out);
}